// round 1
// baseline (speedup 1.0000x reference)
#include <cuda_runtime.h>
#include <cstdint>

// Problem constants
#define BB      8
#define NP      4096          // points per cloud
#define NS      1024          // FPS samples per cloud
#define NC      (BB*NS)       // 8192 total centers
#define KNBR    64
#define CIN     64
#define HH      128
#define R2      0.04f
#define CAP     768           // candidate buffer per warp (expected ~140 in-radius)

// ---------------- device scratch (no allocations allowed) ----------------
__device__ float g_feat[BB*NP*HH];     // x @ W1[:64,:]  (16 MB)
__device__ int   d_fps[NC];            // FPS indices (local to cloud)
__device__ int   d_nbr[NC*KNBR];       // neighbor GLOBAL point indices
__device__ int   d_cnt[NC];            // valid neighbor count (<=64)
__device__ float d_ctr[NC*3];          // center positions

// squared distance with the same rounding as the reference (no fma contraction)
__device__ __forceinline__ float dist2(float ax,float ay,float az,float bx,float by,float bz){
    float dx = ax-bx, dy = ay-by, dz = az-bz;
    return __fadd_rn(__fadd_rn(__fmul_rn(dx,dx),__fmul_rn(dy,dy)),__fmul_rn(dz,dz));
}

// ---------------- K1: fused FPS (blocks 0..7) + g = x@W1a (blocks 8..263) ----
__global__ __launch_bounds__(1024)
void k1_fps_g(const float* __restrict__ pos, const float* __restrict__ x,
              const float* __restrict__ W1)
{
    extern __shared__ float sm[];
    int tid = threadIdx.x;

    if (blockIdx.x < BB) {
        // -------- FPS for cloud b --------
        int b = blockIdx.x;
        float* px = sm;            // 4096
        float* py = sm + 4096;
        float* pz = sm + 8192;
        float* swv = sm + 12288;   // 32
        int*   swi = (int*)(sm + 12320);
        int*   s_last = (int*)(sm + 12352);

        const float* pb = pos + (size_t)b*NP*3;
        for (int i = tid; i < NP; i += 1024) {
            px[i] = pb[i*3+0]; py[i] = pb[i*3+1]; pz[i] = pb[i*3+2];
        }
        if (tid == 0) { d_fps[b*NS] = 0; s_last[0] = 0; }
        float m0 = 1e10f, m1 = 1e10f, m2 = 1e10f, m3 = 1e10f;
        __syncthreads();

        int lane = tid & 31, warp = tid >> 5;
        for (int step = 1; step < NS; ++step) {
            int last = s_last[0];
            float lx = px[last], ly = py[last], lz = pz[last];
            float bv = -1.0f; int bi = 0;
            {
                int i = tid;
                float d = dist2(px[i],py[i],pz[i],lx,ly,lz);
                m0 = fminf(m0,d); if (m0 > bv) { bv = m0; bi = i; }
            }
            {
                int i = tid + 1024;
                float d = dist2(px[i],py[i],pz[i],lx,ly,lz);
                m1 = fminf(m1,d); if (m1 > bv) { bv = m1; bi = i; }
            }
            {
                int i = tid + 2048;
                float d = dist2(px[i],py[i],pz[i],lx,ly,lz);
                m2 = fminf(m2,d); if (m2 > bv) { bv = m2; bi = i; }
            }
            {
                int i = tid + 3072;
                float d = dist2(px[i],py[i],pz[i],lx,ly,lz);
                m3 = fminf(m3,d); if (m3 > bv) { bv = m3; bi = i; }
            }
            // warp argmax (value desc, index asc on ties)
            #pragma unroll
            for (int off = 16; off; off >>= 1) {
                float ov = __shfl_down_sync(0xffffffffu, bv, off);
                int   oi = __shfl_down_sync(0xffffffffu, bi, off);
                if (ov > bv || (ov == bv && oi < bi)) { bv = ov; bi = oi; }
            }
            if (lane == 0) { swv[warp] = bv; swi[warp] = bi; }
            __syncthreads();
            if (tid < 32) {
                bv = swv[tid]; bi = swi[tid];
                #pragma unroll
                for (int off = 16; off; off >>= 1) {
                    float ov = __shfl_down_sync(0xffffffffu, bv, off);
                    int   oi = __shfl_down_sync(0xffffffffu, bi, off);
                    if (ov > bv || (ov == bv && oi < bi)) { bv = ov; bi = oi; }
                }
                if (tid == 0) { s_last[0] = bi; d_fps[b*NS + step] = bi; }
            }
            __syncthreads();
        }
    } else {
        // -------- g = x @ W1[:64,:]  : block handles 128 rows --------
        float* sW = sm;            // 64*128
        float* sx = sm + 8192;     // 128*64
        int rbase = (blockIdx.x - BB) * 128;
        for (int i = tid; i < 64*HH; i += 1024) sW[i] = W1[i];
        for (int i = tid; i < 128*CIN; i += 1024) {
            int r = i >> 6, c = i & 63;
            sx[i] = x[(size_t)(rbase + r)*CIN + c];
        }
        __syncthreads();
        #pragma unroll 4
        for (int p = 0; p < 16; ++p) {
            int o = tid + p*1024;
            int r = o >> 7, col = o & 127;
            float acc = 0.0f;
            const float* xr = sx + r*CIN;
            #pragma unroll 8
            for (int c = 0; c < CIN; ++c)
                acc = fmaf(xr[c], sW[c*HH + col], acc);
            g_feat[(size_t)(rbase + r)*HH + col] = acc;
        }
    }
}

// ---------------- K2: radius ball query (top-64 nearest within R) -------------
__global__ __launch_bounds__(256)
void k2_ball(const float* __restrict__ pos, float* __restrict__ out, int mode)
{
    extern __shared__ unsigned char smraw[];
    float* px = (float*)smraw;
    float* py = px + NP;
    float* pz = py + NP;
    unsigned long long* cball = (unsigned long long*)(smraw + 3*NP*4);

    int tid = threadIdx.x, lane = tid & 31, wid = tid >> 5;
    int cg = blockIdx.x * 8 + wid;          // global center id
    int cloud = cg >> 10;

    const float* pb = pos + (size_t)cloud*NP*3;
    for (int i = tid; i < NP; i += 256) {
        px[i] = pb[i*3+0]; py[i] = pb[i*3+1]; pz[i] = pb[i*3+2];
    }
    __syncthreads();

    int ci = d_fps[cg];
    float cx = px[ci], cy = py[ci], cz = pz[ci];
    if (lane == 0) {
        d_ctr[cg*3+0] = cx; d_ctr[cg*3+1] = cy; d_ctr[cg*3+2] = cz;
        if (mode & 1) {
            out[NC*HH + cg*3+0] = cx;
            out[NC*HH + cg*3+1] = cy;
            out[NC*HH + cg*3+2] = cz;
        }
        if (mode & 2) out[NC*HH + NC*3 + cg] = (float)cloud;
    }

    unsigned long long* cb = cball + (size_t)wid * CAP;
    unsigned cnt = 0;
    for (int j = lane; j < NP; j += 32) {
        float d2 = dist2(px[j],py[j],pz[j],cx,cy,cz);
        bool in = (d2 <= R2);
        unsigned m = __ballot_sync(0xffffffffu, in);
        if (in) {
            unsigned o = cnt + __popc(m & ((1u << lane) - 1u));
            if (o < CAP)
                cb[o] = ((unsigned long long)__float_as_uint(d2) << 32) | (unsigned)j;
        }
        cnt += __popc(m);
    }
    if (cnt > CAP) cnt = CAP;

    int base = cg * KNBR;
    if (cnt <= KNBR) {
        for (int t = lane; t < (int)cnt; t += 32)
            d_nbr[base + t] = cloud*NP + (int)(unsigned)(cb[t] & 0xffffffffull);
        if (lane == 0) d_cnt[cg] = (int)cnt;
    } else {
        for (int t = 0; t < KNBR; ++t) {
            unsigned long long bv = ~0ull; int bp = -1;
            for (int p = lane; p < (int)cnt; p += 32) {
                unsigned long long v = cb[p];
                if (v < bv) { bv = v; bp = p; }
            }
            #pragma unroll
            for (int off = 16; off; off >>= 1) {
                unsigned long long ov = __shfl_xor_sync(0xffffffffu, bv, off);
                int op = __shfl_xor_sync(0xffffffffu, bp, off);
                if (ov < bv) { bv = ov; bp = op; }
            }
            if (lane == 0) {
                d_nbr[base + t] = cloud*NP + (int)(unsigned)(bv & 0xffffffffull);
                cb[bp] = ~0ull;
            }
            __syncwarp();
        }
        if (lane == 0) d_cnt[cg] = KNBR;
    }
}

// ---------------- K3: MLP (67->128->128) + max aggregation --------------------
#define W2S 132   // padded shared stride for transposed W2
__global__ __launch_bounds__(128)
void k3_mlp(const float* __restrict__ pos,
            const float* __restrict__ W1, const float* __restrict__ b1,
            const float* __restrict__ W2, const float* __restrict__ b2,
            float* __restrict__ out, int out_size)
{
    extern __shared__ float sm3[];
    float* sW2t = sm3;                 // [128][132], sW2t[t*132 + c] = W2[c][t]
    float* sh1  = sm3 + HH*W2S;        // [4][128]

    int t  = threadIdx.x;
    int cg = blockIdx.x;

    // load W2 transposed
    for (int i = t; i < HH*HH; i += 128) {
        int c = i >> 7, col = i & 127;
        sW2t[col*W2S + c] = W2[i];
    }
    int   cnt = d_cnt[cg];
    float cx = d_ctr[cg*3+0], cy = d_ctr[cg*3+1], cz = d_ctr[cg*3+2];
    float b1t = b1[t], b2t = b2[t];
    float w1x = W1[64*HH + t], w1y = W1[65*HH + t], w1z = W1[66*HH + t];
    float m = 0.0f;   // outputs are relu'd (>=0) and >=1 valid neighbor always
    __syncthreads();

    for (int kb = 0; kb < cnt; kb += 4) {
        #pragma unroll
        for (int i = 0; i < 4; ++i) {
            int k = kb + i;
            float h = 0.0f;
            if (k < cnt) {
                int gj = d_nbr[cg*KNBR + k];
                float xj = __ldg(&pos[(size_t)gj*3+0]);
                float yj = __ldg(&pos[(size_t)gj*3+1]);
                float zj = __ldg(&pos[(size_t)gj*3+2]);
                float v = g_feat[(size_t)gj*HH + t] + b1t;
                v = fmaf(xj - cx, w1x, v);
                v = fmaf(yj - cy, w1y, v);
                v = fmaf(zj - cz, w1z, v);
                h = fmaxf(v, 0.0f);
            }
            sh1[i*HH + t] = h;
        }
        __syncthreads();

        float a0 = b2t, a1 = b2t, a2 = b2t, a3 = b2t;
        const float* wrow = sW2t + t*W2S;
        #pragma unroll
        for (int c = 0; c < HH; c += 4) {
            float4 w  = *(const float4*)(wrow + c);
            float4 h0 = *(const float4*)(sh1 + 0*HH + c);
            float4 h1 = *(const float4*)(sh1 + 1*HH + c);
            float4 h2 = *(const float4*)(sh1 + 2*HH + c);
            float4 h3 = *(const float4*)(sh1 + 3*HH + c);
            a0 = fmaf(h0.x, w.x, a0); a0 = fmaf(h0.y, w.y, a0);
            a0 = fmaf(h0.z, w.z, a0); a0 = fmaf(h0.w, w.w, a0);
            a1 = fmaf(h1.x, w.x, a1); a1 = fmaf(h1.y, w.y, a1);
            a1 = fmaf(h1.z, w.z, a1); a1 = fmaf(h1.w, w.w, a1);
            a2 = fmaf(h2.x, w.x, a2); a2 = fmaf(h2.y, w.y, a2);
            a2 = fmaf(h2.z, w.z, a2); a2 = fmaf(h2.w, w.w, a2);
            a3 = fmaf(h3.x, w.x, a3); a3 = fmaf(h3.y, w.y, a3);
            a3 = fmaf(h3.z, w.z, a3); a3 = fmaf(h3.w, w.w, a3);
        }
        if (kb + 0 < cnt) m = fmaxf(m, a0);
        if (kb + 1 < cnt) m = fmaxf(m, a1);
        if (kb + 2 < cnt) m = fmaxf(m, a2);
        if (kb + 3 < cnt) m = fmaxf(m, a3);
        __syncthreads();
    }
    int o = cg*HH + t;
    if (o < out_size) out[o] = m;
}

// ---------------- tail zero fill (if out buffer larger than known outputs) ----
__global__ void k_fill(float* out, int start, int n) {
    int i = blockIdx.x * 256 + threadIdx.x;
    if (i < n) out[start + i] = 0.0f;
}

// ---------------- launch --------------------------------------------------
extern "C" void kernel_launch(void* const* d_in, const int* in_sizes, int n_in,
                              void* d_out, int out_size)
{
    const float* x   = (const float*)d_in[0];
    const float* pos = (const float*)d_in[1];
    const float* W1  = (const float*)d_in[2];
    const float* b1  = (const float*)d_in[3];
    const float* W2  = (const float*)d_in[4];
    const float* b2  = (const float*)d_in[5];
    float* out = (float*)d_out;

    size_t sm1 = 65536;                        // max(FPS 49.5KB, g 64KB)
    size_t sm2 = 3*NP*4 + 8*(size_t)CAP*8;     // 48KB pos + 48KB candidates
    size_t sm3 = (HH*W2S + 4*HH) * 4;          // ~68KB
    cudaFuncSetAttribute(k1_fps_g, cudaFuncAttributeMaxDynamicSharedMemorySize, (int)sm1);
    cudaFuncSetAttribute(k2_ball,  cudaFuncAttributeMaxDynamicSharedMemorySize, (int)sm2);
    cudaFuncSetAttribute(k3_mlp,   cudaFuncAttributeMaxDynamicSharedMemorySize, (int)sm3);

    int mode = 0;
    int used = NC*HH;
    if (out_size >= NC*HH + NC*3)           { mode |= 1; used = NC*HH + NC*3; }
    if (out_size >= NC*HH + NC*3 + NC)      { mode |= 2; used = NC*HH + NC*3 + NC; }

    k1_fps_g<<<BB + (BB*NP/128), 1024, sm1>>>(pos, x, W1);
    k2_ball<<<NC/8, 256, sm2>>>(pos, out, mode);
    k3_mlp<<<NC, 128, sm3>>>(pos, W1, b1, W2, b2, out, out_size);

    if (out_size > used) {
        int n = out_size - used;
        k_fill<<<(n + 255)/256, 256>>>(out, used, n);
    }
}

// round 2
// speedup vs baseline: 1.1140x; 1.1140x over previous
#include <cuda_runtime.h>
#include <cstdint>

#define BB      8
#define NP      4096
#define NS      1024
#define NC      (BB*NS)
#define KNBR    64
#define CIN     64
#define HH      128
#define R2      0.04f
#define CAP     768
#define SH1S    68            // sh1 row stride (floats): 16B aligned, gcd(68,32)=4
#define W2T     129           // transposed W2 row stride (floats): odd -> conflict-free
#define NCPB    8             // centers per k3 block

// ---------------- device scratch ----------------
__device__ float g_feat[BB*NP*HH];
__device__ int   d_fps[NC];
__device__ int   d_nbr[NC*KNBR];
__device__ int   d_cnt[NC];
__device__ float d_ctr[NC*3];

__device__ __forceinline__ float dist2(float ax,float ay,float az,float bx,float by,float bz){
    float dx = ax-bx, dy = ay-by, dz = az-bz;
    return __fadd_rn(__fadd_rn(__fmul_rn(dx,dx),__fmul_rn(dy,dy)),__fmul_rn(dz,dz));
}

// packed f32x2 helpers (sm_103a FFMA2)
__device__ __forceinline__ unsigned long long packf2(float lo, float hi){
    unsigned long long r;
    asm("mov.b64 %0, {%1, %2};" : "=l"(r) : "f"(lo), "f"(hi));
    return r;
}
__device__ __forceinline__ void unpackf2(unsigned long long v, float& lo, float& hi){
    asm("mov.b64 {%0, %1}, %2;" : "=f"(lo), "=f"(hi) : "l"(v));
}
__device__ __forceinline__ unsigned long long ffma2(unsigned long long a, unsigned long long b, unsigned long long c){
    unsigned long long d;
    asm("fma.rn.f32x2 %0, %1, %2, %3;" : "=l"(d) : "l"(a), "l"(b), "l"(c));
    return d;
}

// ---------------- K1: FPS (blocks 0..7, registers+atomic reduce) + g = x@W1a ----
__global__ __launch_bounds__(256)
void k1_fps_g(const float* __restrict__ pos, const float* __restrict__ x,
              const float* __restrict__ W1)
{
    extern __shared__ float sm[];
    int tid = threadIdx.x;

    if (blockIdx.x < BB) {
        int b = blockIdx.x;
        float* px = sm;
        float* py = sm + NP;
        float* pz = sm + 2*NP;
        unsigned long long* sbest = (unsigned long long*)(sm + 3*NP); // [3]

        const float* pb = pos + (size_t)b*NP*3;
        for (int i = tid; i < NP; i += 256) {
            px[i] = pb[i*3+0]; py[i] = pb[i*3+1]; pz[i] = pb[i*3+2];
        }
        if (tid == 0) {
            d_fps[b*NS] = 0;
            sbest[0] = 0ull; sbest[1] = 0ull; sbest[2] = 0ull;
        }
        __syncthreads();

        // positions in registers: thread owns points (tid<<4)+t
        float rx[16], ry[16], rz[16], md[16];
        int ibase = tid << 4;
        #pragma unroll
        for (int t = 0; t < 16; ++t) {
            rx[t] = px[ibase+t]; ry[t] = py[ibase+t]; rz[t] = pz[ibase+t];
            md[t] = 1e10f;
        }

        int lane = tid & 31;
        int last = 0;
        for (int s = 1; s < NS; ++s) {
            float lx = px[last], ly = py[last], lz = pz[last];
            #pragma unroll
            for (int t = 0; t < 16; ++t) {
                float d = dist2(rx[t], ry[t], rz[t], lx, ly, lz);
                md[t] = fminf(md[t], d);
            }
            float bv = md[0]; int bt = 0;
            #pragma unroll
            for (int t = 1; t < 16; ++t)
                if (md[t] > bv) { bv = md[t]; bt = t; }
            unsigned long long p =
                ((unsigned long long)__float_as_uint(bv) << 32) |
                (unsigned)(NP - 1 - (ibase + bt));
            #pragma unroll
            for (int off = 16; off; off >>= 1) {
                unsigned long long o = __shfl_xor_sync(0xffffffffu, p, off);
                if (o > p) p = o;
            }
            int buf = s % 3;
            if (lane == 0) atomicMax(&sbest[buf], p);
            __syncthreads();
            unsigned long long w = sbest[buf];
            if (tid == 0) sbest[(s + 2) % 3] = 0ull;   // safe: read 1 step ago
            last = NP - 1 - (int)(unsigned)(w & 0xffffffffull);
            if (tid == 0) d_fps[b*NS + s] = last;
        }
    } else {
        // g = x @ W1[:64,:], 32 rows per block
        float* sW = sm;            // 64*128 = 32KB
        float* sx = sm + 64*HH;    // 32*64  = 8KB
        int rbase = (blockIdx.x - BB) * 32;
        for (int i = tid; i < 64*HH; i += 256) sW[i] = W1[i];
        for (int i = tid; i < 32*CIN; i += 256) {
            int r = i >> 6, c = i & 63;
            sx[i] = x[(size_t)(rbase + r)*CIN + c];
        }
        __syncthreads();
        #pragma unroll
        for (int pimg = 0; pimg < 16; ++pimg) {
            int o = tid + pimg*256;
            int r = o >> 7, col = o & 127;
            float acc = 0.0f;
            const float* xr = sx + r*CIN;
            #pragma unroll 16
            for (int c = 0; c < CIN; ++c)
                acc = fmaf(xr[c], sW[c*HH + col], acc);
            g_feat[(size_t)(rbase + r)*HH + col] = acc;
        }
    }
}

// ---------------- K2: radius ball query (top-64 nearest within R) -------------
__global__ __launch_bounds__(256)
void k2_ball(const float* __restrict__ pos, float* __restrict__ out, int mode)
{
    extern __shared__ unsigned char smraw[];
    float* px = (float*)smraw;
    float* py = px + NP;
    float* pz = py + NP;
    unsigned long long* cball = (unsigned long long*)(smraw + 3*NP*4);

    int tid = threadIdx.x, lane = tid & 31, wid = tid >> 5;
    int cg = blockIdx.x * 8 + wid;
    int cloud = cg >> 10;

    const float* pb = pos + (size_t)cloud*NP*3;
    for (int i = tid; i < NP; i += 256) {
        px[i] = pb[i*3+0]; py[i] = pb[i*3+1]; pz[i] = pb[i*3+2];
    }
    __syncthreads();

    int ci = d_fps[cg];
    float cx = px[ci], cy = py[ci], cz = pz[ci];
    if (lane == 0) {
        d_ctr[cg*3+0] = cx; d_ctr[cg*3+1] = cy; d_ctr[cg*3+2] = cz;
        if (mode & 1) {
            out[NC*HH + cg*3+0] = cx;
            out[NC*HH + cg*3+1] = cy;
            out[NC*HH + cg*3+2] = cz;
        }
        if (mode & 2) out[NC*HH + NC*3 + cg] = (float)cloud;
    }

    unsigned long long* cb = cball + (size_t)wid * CAP;
    unsigned cnt = 0;
    for (int j = lane; j < NP; j += 32) {
        float d2 = dist2(px[j],py[j],pz[j],cx,cy,cz);
        bool in = (d2 <= R2);
        unsigned m = __ballot_sync(0xffffffffu, in);
        if (in) {
            unsigned o = cnt + __popc(m & ((1u << lane) - 1u));
            if (o < CAP)
                cb[o] = ((unsigned long long)__float_as_uint(d2) << 32) | (unsigned)j;
        }
        cnt += __popc(m);
    }
    if (cnt > CAP) cnt = CAP;

    int base = cg * KNBR;
    if (cnt <= KNBR) {
        for (int t = lane; t < (int)cnt; t += 32)
            d_nbr[base + t] = cloud*NP + (int)(unsigned)(cb[t] & 0xffffffffull);
        if (lane == 0) d_cnt[cg] = (int)cnt;
    } else {
        for (int t = 0; t < KNBR; ++t) {
            unsigned long long bv = ~0ull; int bp = -1;
            for (int p = lane; p < (int)cnt; p += 32) {
                unsigned long long v = cb[p];
                if (v < bv) { bv = v; bp = p; }
            }
            #pragma unroll
            for (int off = 16; off; off >>= 1) {
                unsigned long long ov = __shfl_xor_sync(0xffffffffu, bv, off);
                int op = __shfl_xor_sync(0xffffffffu, bp, off);
                if (ov < bv) { bv = ov; bp = op; }
            }
            if (lane == 0) {
                d_nbr[base + t] = cloud*NP + (int)(unsigned)(bv & 0xffffffffull);
                cb[bp] = ~0ull;
            }
            __syncwarp();
        }
        if (lane == 0) d_cnt[cg] = KNBR;
    }
}

// ---------------- K3: MLP (67->128->128) + max aggregation, FFMA2 -------------
__global__ __launch_bounds__(128)
void k3_mlp(const float* __restrict__ pos,
            const float* __restrict__ W1, const float* __restrict__ b1,
            const float* __restrict__ W2, const float* __restrict__ b2,
            float* __restrict__ out, int out_size)
{
    extern __shared__ float sm3[];
    float* sW2t = sm3;                        // [128][W2T], sW2t[col*W2T+c] = W2[c][col]
    float* sh1  = sm3 + HH*W2T;               // [128][SH1S]  (c-major, n contiguous)
    int*   snbr = (int*)(sh1 + HH*SH1S);      // 64
    float* sctr = (float*)(snbr + KNBR);      // cx,cy,cz
    int*   scnt = (int*)(sctr + 3);

    int t = threadIdx.x;

    for (int i = t; i < HH*HH; i += 128) {
        int c = i >> 7, col = i & 127;
        sW2t[col*W2T + c] = W2[i];
    }
    float b1t = b1[t], b2t = b2[t];
    float w1x = W1[64*HH + t], w1y = W1[65*HH + t], w1z = W1[66*HH + t];

    for (int cc = 0; cc < NCPB; ++cc) {
        int cg = blockIdx.x * NCPB + cc;
        __syncthreads();   // sh1 reads of prev center done
        if (t < KNBR) snbr[t] = d_nbr[cg*KNBR + t];
        else if (t < KNBR+3) sctr[t-KNBR] = d_ctr[cg*3 + (t-KNBR)];
        else if (t == KNBR+3) *scnt = d_cnt[cg];
        __syncthreads();
        int cnt = *scnt;
        float cx = sctr[0], cy = sctr[1], cz = sctr[2];

        // layer 1: h1[c=t][n]
        for (int n = 0; n < KNBR; ++n) {
            float h = 0.0f;
            if (n < cnt) {
                int gj = snbr[n];
                float xj = __ldg(&pos[(size_t)gj*3+0]);
                float yj = __ldg(&pos[(size_t)gj*3+1]);
                float zj = __ldg(&pos[(size_t)gj*3+2]);
                float v = g_feat[(size_t)gj*HH + t] + b1t;
                v = fmaf(xj - cx, w1x, v);
                v = fmaf(yj - cy, w1y, v);
                v = fmaf(zj - cz, w1z, v);
                h = fmaxf(v, 0.0f);
            }
            sh1[t*SH1S + n] = h;
        }
        __syncthreads();

        // layer 2: thread t = out channel, FFMA2 over neighbor pairs
        float m = 0.0f;
        const float* wcol = sW2t + t*W2T;
        #pragma unroll 1
        for (int half = 0; half < 2; ++half) {
            unsigned long long acc[16];
            unsigned long long b2p = packf2(b2t, b2t);
            #pragma unroll
            for (int j = 0; j < 16; ++j) acc[j] = b2p;
            const float* hb = sh1 + half*32;
            #pragma unroll 4
            for (int c = 0; c < HH; ++c) {
                float wv = wcol[c];
                unsigned long long wd = packf2(wv, wv);
                const float4* hp = (const float4*)(hb + c*SH1S);
                #pragma unroll
                for (int g = 0; g < 8; ++g) {
                    float4 h4 = hp[g];
                    acc[2*g]   = ffma2(packf2(h4.x, h4.y), wd, acc[2*g]);
                    acc[2*g+1] = ffma2(packf2(h4.z, h4.w), wd, acc[2*g+1]);
                }
            }
            #pragma unroll
            for (int j = 0; j < 16; ++j) {
                float lo, hi; unpackf2(acc[j], lo, hi);
                int n0 = half*32 + 2*j;
                if (n0     < cnt) m = fmaxf(m, lo);
                if (n0 + 1 < cnt) m = fmaxf(m, hi);
            }
        }
        int o = cg*HH + t;
        if (o < out_size) out[o] = m;
    }
}

__global__ void k_fill(float* out, int start, int n) {
    int i = blockIdx.x * 256 + threadIdx.x;
    if (i < n) out[start + i] = 0.0f;
}

// ---------------- launch --------------------------------------------------
extern "C" void kernel_launch(void* const* d_in, const int* in_sizes, int n_in,
                              void* d_out, int out_size)
{
    const float* x   = (const float*)d_in[0];
    const float* pos = (const float*)d_in[1];
    const float* W1  = (const float*)d_in[2];
    const float* b1  = (const float*)d_in[3];
    const float* W2  = (const float*)d_in[4];
    const float* b2  = (const float*)d_in[5];
    float* out = (float*)d_out;

    size_t sm1 = (3*NP)*4 + 64 + 64*HH*4 + 32*CIN*4; // covers both variants (~90KB upper bound)
    // separate sizes: FPS = 48KB+32B ; g = 40KB. use max + pad
    sm1 = 3*NP*4 + 64;                 // 49216
    size_t smg = (64*HH + 32*CIN)*4;   // 40960
    if (smg > sm1) sm1 = smg;
    size_t sm2 = 3*NP*4 + 8*(size_t)CAP*8;
    size_t sm3 = (HH*W2T + HH*SH1S)*4 + KNBR*4 + 4*4;
    cudaFuncSetAttribute(k1_fps_g, cudaFuncAttributeMaxDynamicSharedMemorySize, (int)sm1);
    cudaFuncSetAttribute(k2_ball,  cudaFuncAttributeMaxDynamicSharedMemorySize, (int)sm2);
    cudaFuncSetAttribute(k3_mlp,   cudaFuncAttributeMaxDynamicSharedMemorySize, (int)sm3);

    int mode = 0;
    int used = NC*HH;
    if (out_size >= NC*HH + NC*3)      { mode |= 1; used = NC*HH + NC*3; }
    if (out_size >= NC*HH + NC*3 + NC) { mode |= 2; used = NC*HH + NC*3 + NC; }

    k1_fps_g<<<BB + (BB*NP/32), 256, sm1>>>(pos, x, W1);
    k2_ball<<<NC/8, 256, sm2>>>(pos, out, mode);
    k3_mlp<<<NC/NCPB, 128, sm3>>>(pos, W1, b1, W2, b2, out, out_size);

    if (out_size > used) {
        int n = out_size - used;
        k_fill<<<(n + 255)/256, 256>>>(out, used, n);
    }
}

// round 4
// speedup vs baseline: 1.7169x; 1.5412x over previous
#include <cuda_runtime.h>
#include <cstdint>

#define BB      8
#define NP      4096
#define NS      1024
#define NC      (BB*NS)
#define KNBR    64
#define CIN     64
#define HH      128
#define R2      0.04f
#define CAP     768

// ---------------- device scratch ----------------
__device__ float g_feat[BB*NP*HH];     // x @ W1[:64,:]
__device__ int   d_fps[NC];
__device__ int   d_nbr[NC*KNBR];       // padded to 64 per center (dup of nbr 0)
__device__ int   d_cnt[NC];
__device__ float d_ctr[NC*3];

__device__ __forceinline__ float dist2(float ax,float ay,float az,float bx,float by,float bz){
    float dx = ax-bx, dy = ay-by, dz = az-bz;
    return __fadd_rn(__fadd_rn(__fmul_rn(dx,dx),__fmul_rn(dy,dy)),__fmul_rn(dz,dz));
}

// packed f32x2 helpers (per-lane IEEE rn == scalar rounding)
__device__ __forceinline__ unsigned long long packf2(float lo, float hi){
    unsigned long long r;
    asm("mov.b64 %0, {%1, %2};" : "=l"(r) : "f"(lo), "f"(hi));
    return r;
}
__device__ __forceinline__ void unpackf2(unsigned long long v, float& lo, float& hi){
    asm("mov.b64 {%0, %1}, %2;" : "=f"(lo), "=f"(hi) : "l"(v));
}
__device__ __forceinline__ unsigned long long addf2(unsigned long long a, unsigned long long b){
    unsigned long long d; asm("add.rn.f32x2 %0, %1, %2;" : "=l"(d) : "l"(a), "l"(b)); return d;
}
__device__ __forceinline__ unsigned long long mulf2(unsigned long long a, unsigned long long b){
    unsigned long long d; asm("mul.rn.f32x2 %0, %1, %2;" : "=l"(d) : "l"(a), "l"(b)); return d;
}
__device__ __forceinline__ unsigned long long ffma2(unsigned long long a, unsigned long long b, unsigned long long c){
    unsigned long long d; asm("fma.rn.f32x2 %0, %1, %2, %3;" : "=l"(d) : "l"(a), "l"(b), "l"(c)); return d;
}
__device__ __forceinline__ uint32_t smem_u32(const void* p){
    uint32_t a;
    asm("{ .reg .u64 t; cvta.to.shared.u64 t, %1; cvt.u32.u64 %0, t; }" : "=r"(a) : "l"(p));
    return a;
}
#define LDSH64(dst, addr, IMM) \
    asm volatile("ld.shared.b64 %0, [%1+%2];" : "=l"(dst) : "r"(addr), "n"(IMM))

// ---------------- K1: FPS (blocks 0..7) + g = x@W1a (blocks 8..1031) ----------
__global__ __launch_bounds__(256)
void k1_fps_g(const float* __restrict__ pos, const float* __restrict__ x,
              const float* __restrict__ W1)
{
    extern __shared__ float sm[];
    int tid = threadIdx.x;

    if (blockIdx.x < BB) {
        int b = blockIdx.x;
        float* px = sm;
        float* py = sm + NP;
        float* pz = sm + 2*NP;
        unsigned long long* sbuf = (unsigned long long*)(sm + 3*NP); // [2][8]

        const float* pb = pos + (size_t)b*NP*3;
        for (int i = tid; i < NP; i += 256) {
            px[i] = pb[i*3+0]; py[i] = pb[i*3+1]; pz[i] = pb[i*3+2];
        }
        if (tid == 0) d_fps[b*NS] = 0;
        __syncthreads();

        int ibase = tid << 4;
        unsigned long long rpx[8], rpy[8], rpz[8];
        float md[16];
        #pragma unroll
        for (int j = 0; j < 8; ++j) {
            rpx[j] = packf2(px[ibase+2*j], px[ibase+2*j+1]);
            rpy[j] = packf2(py[ibase+2*j], py[ibase+2*j+1]);
            rpz[j] = packf2(pz[ibase+2*j], pz[ibase+2*j+1]);
        }
        #pragma unroll
        for (int t = 0; t < 16; ++t) md[t] = 1e10f;

        int lane = tid & 31, warp = tid >> 5;
        int last = 0;
        for (int s = 1; s < NS; ++s) {
            float lx = px[last], ly = py[last], lz = pz[last];
            unsigned long long nx = packf2(-lx,-lx), ny = packf2(-ly,-ly), nz = packf2(-lz,-lz);
            #pragma unroll
            for (int j = 0; j < 8; ++j) {
                unsigned long long dx = addf2(rpx[j], nx);
                unsigned long long dy = addf2(rpy[j], ny);
                unsigned long long dz = addf2(rpz[j], nz);
                unsigned long long sD = addf2(addf2(mulf2(dx,dx), mulf2(dy,dy)), mulf2(dz,dz));
                float s0, s1; unpackf2(sD, s0, s1);
                md[2*j]   = fminf(md[2*j],   s0);
                md[2*j+1] = fminf(md[2*j+1], s1);
            }
            float bv = md[0]; int bt = 0;
            #pragma unroll
            for (int t = 1; t < 16; ++t)
                if (md[t] > bv) { bv = md[t]; bt = t; }

            // warp argmax via redux (lane order == point order => first-max kept)
            unsigned vbits = __float_as_uint(bv);
            unsigned vm = __reduce_max_sync(0xffffffffu, vbits);
            unsigned msk = __ballot_sync(0xffffffffu, vbits == vm);
            int src = __ffs(msk) - 1;
            int bidx = __shfl_sync(0xffffffffu, ibase + bt, src);

            unsigned long long* slot = sbuf + (s & 1)*8;
            if (lane == 0)
                slot[warp] = ((unsigned long long)vm << 32) | (unsigned)(NP - 1 - bidx);
            __syncthreads();
            unsigned long long w = slot[0];
            #pragma unroll
            for (int k = 1; k < 8; ++k) { unsigned long long v = slot[k]; if (v > w) w = v; }
            last = NP - 1 - (int)(unsigned)(w & 0xffffffffull);
            if (tid == 0) d_fps[b*NS + s] = last;
        }
    } else {
        // g = x @ W1[:64,:], 32 rows per block
        float* sW = sm;
        float* sx = sm + 64*HH;
        int rbase = (blockIdx.x - BB) * 32;
        for (int i = tid; i < 64*HH; i += 256) sW[i] = W1[i];
        for (int i = tid; i < 32*CIN; i += 256) {
            int r = i >> 6, c = i & 63;
            sx[i] = x[(size_t)(rbase + r)*CIN + c];
        }
        __syncthreads();
        #pragma unroll
        for (int pimg = 0; pimg < 16; ++pimg) {
            int o = tid + pimg*256;
            int r = o >> 7, col = o & 127;
            float acc = 0.0f;
            const float* xr = sx + r*CIN;
            #pragma unroll 16
            for (int c = 0; c < CIN; ++c)
                acc = fmaf(xr[c], sW[c*HH + col], acc);
            g_feat[(size_t)(rbase + r)*HH + col] = acc;
        }
    }
}

// ---------------- K2: radius ball query (top-64 nearest within R) -------------
__global__ __launch_bounds__(256)
void k2_ball(const float* __restrict__ pos, float* __restrict__ out, int mode)
{
    extern __shared__ unsigned char smraw[];
    float* px = (float*)smraw;
    float* py = px + NP;
    float* pz = py + NP;
    unsigned long long* cball = (unsigned long long*)(smraw + 3*NP*4);

    int tid = threadIdx.x, lane = tid & 31, wid = tid >> 5;
    int cg = blockIdx.x * 8 + wid;
    int cloud = cg >> 10;

    const float* pb = pos + (size_t)cloud*NP*3;
    for (int i = tid; i < NP; i += 256) {
        px[i] = pb[i*3+0]; py[i] = pb[i*3+1]; pz[i] = pb[i*3+2];
    }
    __syncthreads();

    int ci = d_fps[cg];
    float cx = px[ci], cy = py[ci], cz = pz[ci];
    if (lane == 0) {
        d_ctr[cg*3+0] = cx; d_ctr[cg*3+1] = cy; d_ctr[cg*3+2] = cz;
        if (mode & 1) {
            out[NC*HH + cg*3+0] = cx;
            out[NC*HH + cg*3+1] = cy;
            out[NC*HH + cg*3+2] = cz;
        }
        if (mode & 2) out[NC*HH + NC*3 + cg] = (float)cloud;
    }

    unsigned long long* cb = cball + (size_t)wid * CAP;
    unsigned cnt = 0;
    for (int j = lane; j < NP; j += 32) {
        float d2 = dist2(px[j],py[j],pz[j],cx,cy,cz);
        bool in = (d2 <= R2);
        unsigned m = __ballot_sync(0xffffffffu, in);
        if (in) {
            unsigned o = cnt + __popc(m & ((1u << lane) - 1u));
            if (o < CAP)
                cb[o] = ((unsigned long long)__float_as_uint(d2) << 32) | (unsigned)j;
        }
        cnt += __popc(m);
    }
    if (cnt > CAP) cnt = CAP;

    int base = cg * KNBR;
    if (cnt <= KNBR) {
        int firstIdx = cloud*NP + (int)(unsigned)(cb[0] & 0xffffffffull);
        for (int t = lane; t < KNBR; t += 32)
            d_nbr[base + t] = (t < (int)cnt)
                ? cloud*NP + (int)(unsigned)(cb[t] & 0xffffffffull) : firstIdx;
        if (lane == 0) d_cnt[cg] = (int)cnt;
    } else {
        for (int t = 0; t < KNBR; ++t) {
            unsigned long long bv = ~0ull; int bp = -1;
            for (int p = lane; p < (int)cnt; p += 32) {
                unsigned long long v = cb[p];
                if (v < bv) { bv = v; bp = p; }
            }
            #pragma unroll
            for (int off = 16; off; off >>= 1) {
                unsigned long long ov = __shfl_xor_sync(0xffffffffu, bv, off);
                int op = __shfl_xor_sync(0xffffffffu, bp, off);
                if (ov < bv) { bv = ov; bp = op; }
            }
            if (lane == 0) {
                d_nbr[base + t] = cloud*NP + (int)(unsigned)(bv & 0xffffffffull);
                cb[bp] = ~0ull;
            }
            __syncwarp();
        }
        if (lane == 0) d_cnt[cg] = KNBR;
    }
}

// ---------------- K3: h1 build + FFMA2 register-tiled GEMM + max --------------
// block = 2 centers (N=128 cols), 256 threads, thread tile 8m x 8n (n-pairs)
#define OA      0                   // A dup: [k 128][j 8][tm 16] f32x2 = 131072 B
#define OB      131072              // B h1:  [k 128][n 128] f32   =  65536 B
#define OWB     (OB + 65536)        // float4[128]: (b1, w1x, w1y, w1z) per k
#define ODP     (OWB + 2048)        // float4[128]: dpos per column
#define OGJ     (ODP + 2048)        // int[128]
#define OPART   (OGJ + 512)         // [16 tn][128 m] f32 = 8192 B
#define K3_SMEM (OPART + 8192)      // 209920 B total

__global__ __launch_bounds__(256, 1)
void k3_mlp(const float* __restrict__ pos,
            const float* __restrict__ W1, const float* __restrict__ b1,
            const float* __restrict__ W2, const float* __restrict__ b2,
            float* __restrict__ out)
{
    extern __shared__ char smem[];
    uint32_t sbase = smem_u32(smem);
    int t = threadIdx.x;
    int cg0 = blockIdx.x * 2;

    // A = W2 (row-major [k][m]) pre-duplicated, j-major layout
    for (int idx = t; idx < HH*HH; idx += 256) {
        int k = idx >> 7, m = idx & 127;
        float wv = W2[idx];
        int tm = m >> 3, j = m & 7;
        *(unsigned long long*)(smem + OA + k*1024 + j*128 + tm*8) = packf2(wv, wv);
    }
    if (t < HH) {
        float4 wb;
        wb.x = b1[t];
        wb.y = W1[64*HH + t]; wb.z = W1[65*HH + t]; wb.w = W1[66*HH + t];
        *(float4*)(smem + OWB + t*16) = wb;
        int cgx = cg0 + (t >> 6);
        int gj = d_nbr[cgx*KNBR + (t & 63)];
        *(int*)(smem + OGJ + t*4) = gj;
        float4 dp;
        dp.x = pos[(size_t)gj*3+0] - d_ctr[cgx*3+0];
        dp.y = pos[(size_t)gj*3+1] - d_ctr[cgx*3+1];
        dp.z = pos[(size_t)gj*3+2] - d_ctr[cgx*3+2];
        dp.w = 0.f;
        *(float4*)(smem + ODP + t*16) = dp;
    }
    __syncthreads();

    // build B: h1[k][n], thread = (col n = t&127, k-half = t>>7)
    {
        int n = t & 127, kh = t >> 7;
        int gj = *(int*)(smem + OGJ + n*4);
        float4 dp = *(float4*)(smem + ODP + n*16);
        const float4* grow = (const float4*)(g_feat + (size_t)gj*HH + kh*64);
        const float4* swb = (const float4*)(smem + OWB);
        float* sB = (float*)(smem + OB);
        #pragma unroll 4
        for (int q = 0; q < 16; ++q) {
            float4 g4 = __ldg(grow + q);
            int k0 = kh*64 + q*4;
            float gv[4] = {g4.x, g4.y, g4.z, g4.w};
            #pragma unroll
            for (int r = 0; r < 4; ++r) {
                float4 wb = swb[k0 + r];
                float v = gv[r] + wb.x;
                v = fmaf(dp.x, wb.y, v);
                v = fmaf(dp.y, wb.z, v);
                v = fmaf(dp.z, wb.w, v);
                sB[(k0 + r)*HH + n] = fmaxf(v, 0.0f);
            }
        }
    }
    __syncthreads();

    // GEMM: acc[j 8][p 4] over m = tm*8+j, n-pair = tn*8 + 2p
    int tm = t & 15, tn = t >> 4;
    uint32_t aB = sbase + OA + tm*8;
    uint32_t bB = sbase + OB + tn*32;
    unsigned long long acc[8][4];
    #pragma unroll
    for (int j = 0; j < 8; ++j)
        #pragma unroll
        for (int p = 0; p < 4; ++p) acc[j][p] = 0ull;

    #pragma unroll 2
    for (int k = 0; k < HH; ++k) {
        unsigned long long a[8], b[4];
        LDSH64(a[0], aB, 0);   LDSH64(a[1], aB, 128);
        LDSH64(a[2], aB, 256); LDSH64(a[3], aB, 384);
        LDSH64(a[4], aB, 512); LDSH64(a[5], aB, 640);
        LDSH64(a[6], aB, 768); LDSH64(a[7], aB, 896);
        LDSH64(b[0], bB, 0);  LDSH64(b[1], bB, 8);
        LDSH64(b[2], bB, 16); LDSH64(b[3], bB, 24);
        #pragma unroll
        for (int j = 0; j < 8; ++j)
            #pragma unroll
            for (int p = 0; p < 4; ++p)
                acc[j][p] = ffma2(a[j], b[p], acc[j][p]);
        aB += 1024; bB += 512;
    }

    // per-thread max over its 8 n, write partials
    {
        float* part = (float*)(smem + OPART);
        #pragma unroll
        for (int j = 0; j < 8; ++j) {
            float mx = -1e30f;
            #pragma unroll
            for (int p = 0; p < 4; ++p) {
                float lo, hi; unpackf2(acc[j][p], lo, hi);
                mx = fmaxf(mx, fmaxf(lo, hi));
            }
            part[tn*HH + tm*8 + j] = mx;
        }
    }
    __syncthreads();

    // final reduce: thread -> (center c, channel m)
    {
        const float* part = (const float*)(smem + OPART);
        int c = t >> 7, m = t & 127;
        float mx = part[(c*8)*HH + m];
        #pragma unroll
        for (int i = 1; i < 8; ++i)
            mx = fmaxf(mx, part[(c*8 + i)*HH + m]);
        out[(size_t)(cg0 + c)*HH + m] = fmaxf(mx + b2[m], 0.0f);
    }
}

__global__ void k_fill(float* out, int start, int n) {
    int i = blockIdx.x * 256 + threadIdx.x;
    if (i < n) out[start + i] = 0.0f;
}

// ---------------- launch --------------------------------------------------
extern "C" void kernel_launch(void* const* d_in, const int* in_sizes, int n_in,
                              void* d_out, int out_size)
{
    const float* x   = (const float*)d_in[0];
    const float* pos = (const float*)d_in[1];
    const float* W1  = (const float*)d_in[2];
    const float* b1  = (const float*)d_in[3];
    const float* W2  = (const float*)d_in[4];
    const float* b2  = (const float*)d_in[5];
    float* out = (float*)d_out;

    size_t sm1 = 3*NP*4 + 128;
    size_t smg = (64*HH + 32*CIN)*4;
    if (smg > sm1) sm1 = smg;
    size_t sm2 = 3*NP*4 + 8*(size_t)CAP*8;
    size_t sm3 = K3_SMEM;
    cudaFuncSetAttribute(k1_fps_g, cudaFuncAttributeMaxDynamicSharedMemorySize, (int)sm1);
    cudaFuncSetAttribute(k2_ball,  cudaFuncAttributeMaxDynamicSharedMemorySize, (int)sm2);
    cudaFuncSetAttribute(k3_mlp,   cudaFuncAttributeMaxDynamicSharedMemorySize, (int)sm3);

    int mode = 0;
    int used = NC*HH;
    if (out_size >= NC*HH + NC*3)      { mode |= 1; used = NC*HH + NC*3; }
    if (out_size >= NC*HH + NC*3 + NC) { mode |= 2; used = NC*HH + NC*3 + NC; }

    k1_fps_g<<<BB + 1024, 256, sm1>>>(pos, x, W1);
    k2_ball<<<NC/8, 256, sm2>>>(pos, out, mode);
    k3_mlp<<<NC/2, 256, sm3>>>(pos, W1, b1, W2, b2, out);

    if (out_size > used) {
        int n = out_size - used;
        k_fill<<<(n + 255)/256, 256>>>(out, used, n);
    }
}

// round 5
// speedup vs baseline: 1.8199x; 1.0600x over previous
#include <cuda_runtime.h>
#include <cstdint>

#define BB      8
#define NP      4096
#define NS      1024
#define NC      (BB*NS)
#define KNBR    64
#define CIN     64
#define HH      128
#define R2      0.04f
#define CAP     768

// ---------------- device scratch ----------------
__device__ float g_feat[BB*NP*HH];     // x @ W1[:64,:]
__device__ int   d_fps[NC];
__device__ int   d_nbr[NC*KNBR];       // padded to 64 per center (dup of nbr 0)
__device__ int   d_cnt[NC];
__device__ float d_ctr[NC*3];

__device__ __forceinline__ float dist2(float ax,float ay,float az,float bx,float by,float bz){
    float dx = ax-bx, dy = ay-by, dz = az-bz;
    return __fadd_rn(__fadd_rn(__fmul_rn(dx,dx),__fmul_rn(dy,dy)),__fmul_rn(dz,dz));
}

// packed f32x2 helpers (per-lane IEEE rn == scalar rounding)
__device__ __forceinline__ unsigned long long packf2(float lo, float hi){
    unsigned long long r;
    asm("mov.b64 %0, {%1, %2};" : "=l"(r) : "f"(lo), "f"(hi));
    return r;
}
__device__ __forceinline__ void unpackf2(unsigned long long v, float& lo, float& hi){
    asm("mov.b64 {%0, %1}, %2;" : "=f"(lo), "=f"(hi) : "l"(v));
}
__device__ __forceinline__ unsigned long long addf2(unsigned long long a, unsigned long long b){
    unsigned long long d; asm("add.rn.f32x2 %0, %1, %2;" : "=l"(d) : "l"(a), "l"(b)); return d;
}
__device__ __forceinline__ unsigned long long mulf2(unsigned long long a, unsigned long long b){
    unsigned long long d; asm("mul.rn.f32x2 %0, %1, %2;" : "=l"(d) : "l"(a), "l"(b)); return d;
}
__device__ __forceinline__ unsigned long long ffma2(unsigned long long a, unsigned long long b, unsigned long long c){
    unsigned long long d; asm("fma.rn.f32x2 %0, %1, %2, %3;" : "=l"(d) : "l"(a), "l"(b), "l"(c)); return d;
}
__device__ __forceinline__ uint32_t smem_u32(const void* p){
    uint32_t a;
    asm("{ .reg .u64 t; cvta.to.shared.u64 t, %1; cvt.u32.u64 %0, t; }" : "=r"(a) : "l"(p));
    return a;
}
#define LDSH64(dst, addr, IMM) \
    asm volatile("ld.shared.b64 %0, [%1+%2];" : "=l"(dst) : "r"(addr), "n"(IMM))

// ---------------- K1: FPS (blocks 0..7) + g = x@W1a (blocks 8..1031) ----------
__global__ __launch_bounds__(256)
void k1_fps_g(const float* __restrict__ pos, const float* __restrict__ x,
              const float* __restrict__ W1)
{
    extern __shared__ float sm[];
    int tid = threadIdx.x;

    if (blockIdx.x < BB) {
        int b = blockIdx.x;
        float* px = sm;
        float* py = sm + NP;
        float* pz = sm + 2*NP;
        unsigned long long* sbuf = (unsigned long long*)(sm + 3*NP); // [2][8]

        const float* pb = pos + (size_t)b*NP*3;
        for (int i = tid; i < NP; i += 256) {
            px[i] = pb[i*3+0]; py[i] = pb[i*3+1]; pz[i] = pb[i*3+2];
        }
        if (tid == 0) d_fps[b*NS] = 0;
        __syncthreads();

        int ibase = tid << 4;
        unsigned long long rpx[8], rpy[8], rpz[8];
        float md[16];
        #pragma unroll
        for (int j = 0; j < 8; ++j) {
            rpx[j] = packf2(px[ibase+2*j], px[ibase+2*j+1]);
            rpy[j] = packf2(py[ibase+2*j], py[ibase+2*j+1]);
            rpz[j] = packf2(pz[ibase+2*j], pz[ibase+2*j+1]);
        }
        #pragma unroll
        for (int t = 0; t < 16; ++t) md[t] = 1e10f;

        int lane = tid & 31, warp = tid >> 5;
        int last = 0;
        for (int s = 1; s < NS; ++s) {
            float lx = px[last], ly = py[last], lz = pz[last];
            unsigned long long nx = packf2(-lx,-lx), ny = packf2(-ly,-ly), nz = packf2(-lz,-lz);
            #pragma unroll
            for (int j = 0; j < 8; ++j) {
                unsigned long long dx = addf2(rpx[j], nx);
                unsigned long long dy = addf2(rpy[j], ny);
                unsigned long long dz = addf2(rpz[j], nz);
                unsigned long long sD = addf2(addf2(mulf2(dx,dx), mulf2(dy,dy)), mulf2(dz,dz));
                float s0, s1; unpackf2(sD, s0, s1);
                md[2*j]   = fminf(md[2*j],   s0);
                md[2*j+1] = fminf(md[2*j+1], s1);
            }
            float bv = md[0]; int bt = 0;
            #pragma unroll
            for (int t = 1; t < 16; ++t)
                if (md[t] > bv) { bv = md[t]; bt = t; }

            unsigned vbits = __float_as_uint(bv);
            unsigned vm = __reduce_max_sync(0xffffffffu, vbits);
            unsigned msk = __ballot_sync(0xffffffffu, vbits == vm);
            int src = __ffs(msk) - 1;
            int bidx = __shfl_sync(0xffffffffu, ibase + bt, src);

            unsigned long long* slot = sbuf + (s & 1)*8;
            if (lane == 0)
                slot[warp] = ((unsigned long long)vm << 32) | (unsigned)(NP - 1 - bidx);
            __syncthreads();
            unsigned long long w = slot[0];
            #pragma unroll
            for (int k = 1; k < 8; ++k) { unsigned long long v = slot[k]; if (v > w) w = v; }
            last = NP - 1 - (int)(unsigned)(w & 0xffffffffull);
            if (tid == 0) d_fps[b*NS + s] = last;
        }
    } else {
        // g = x @ W1[:64,:], 32 rows per block
        float* sW = sm;
        float* sx = sm + 64*HH;
        int rbase = (blockIdx.x - BB) * 32;
        for (int i = tid; i < 64*HH; i += 256) sW[i] = W1[i];
        for (int i = tid; i < 32*CIN; i += 256) {
            int r = i >> 6, c = i & 63;
            sx[i] = x[(size_t)(rbase + r)*CIN + c];
        }
        __syncthreads();
        #pragma unroll
        for (int pimg = 0; pimg < 16; ++pimg) {
            int o = tid + pimg*256;
            int r = o >> 7, col = o & 127;
            float acc = 0.0f;
            const float* xr = sx + r*CIN;
            #pragma unroll 16
            for (int c = 0; c < CIN; ++c)
                acc = fmaf(xr[c], sW[c*HH + col], acc);
            g_feat[(size_t)(rbase + r)*HH + col] = acc;
        }
    }
}

// ---------------- K2: radius ball query (top-64 nearest within R) -------------
__global__ __launch_bounds__(256)
void k2_ball(const float* __restrict__ pos, float* __restrict__ out, int mode)
{
    extern __shared__ unsigned char smraw[];
    float* px = (float*)smraw;
    float* py = px + NP;
    float* pz = py + NP;
    unsigned long long* cball = (unsigned long long*)(smraw + 3*NP*4);

    int tid = threadIdx.x, lane = tid & 31, wid = tid >> 5;
    int cg = blockIdx.x * 8 + wid;
    int cloud = cg >> 10;

    const float* pb = pos + (size_t)cloud*NP*3;
    for (int i = tid; i < NP; i += 256) {
        px[i] = pb[i*3+0]; py[i] = pb[i*3+1]; pz[i] = pb[i*3+2];
    }
    __syncthreads();

    int ci = d_fps[cg];
    float cx = px[ci], cy = py[ci], cz = pz[ci];
    if (lane == 0) {
        d_ctr[cg*3+0] = cx; d_ctr[cg*3+1] = cy; d_ctr[cg*3+2] = cz;
        if (mode & 1) {
            out[NC*HH + cg*3+0] = cx;
            out[NC*HH + cg*3+1] = cy;
            out[NC*HH + cg*3+2] = cz;
        }
        if (mode & 2) out[NC*HH + NC*3 + cg] = (float)cloud;
    }

    unsigned long long* cb = cball + (size_t)wid * CAP;
    unsigned cnt = 0;
    for (int j = lane; j < NP; j += 32) {
        float d2 = dist2(px[j],py[j],pz[j],cx,cy,cz);
        bool in = (d2 <= R2);
        unsigned m = __ballot_sync(0xffffffffu, in);
        if (in) {
            unsigned o = cnt + __popc(m & ((1u << lane) - 1u));
            if (o < CAP)
                cb[o] = ((unsigned long long)__float_as_uint(d2) << 32) | (unsigned)j;
        }
        cnt += __popc(m);
    }
    if (cnt > CAP) cnt = CAP;

    int base = cg * KNBR;
    if (cnt <= KNBR) {
        int firstIdx = cloud*NP + (int)(unsigned)(cb[0] & 0xffffffffull);
        for (int t = lane; t < KNBR; t += 32)
            d_nbr[base + t] = (t < (int)cnt)
                ? cloud*NP + (int)(unsigned)(cb[t] & 0xffffffffull) : firstIdx;
        if (lane == 0) d_cnt[cg] = (int)cnt;
    } else {
        for (int t = 0; t < KNBR; ++t) {
            unsigned long long bv = ~0ull; int bp = -1;
            for (int p = lane; p < (int)cnt; p += 32) {
                unsigned long long v = cb[p];
                if (v < bv) { bv = v; bp = p; }
            }
            #pragma unroll
            for (int off = 16; off; off >>= 1) {
                unsigned long long ov = __shfl_xor_sync(0xffffffffu, bv, off);
                int op = __shfl_xor_sync(0xffffffffu, bp, off);
                if (ov < bv) { bv = ov; bp = op; }
            }
            if (lane == 0) {
                d_nbr[base + t] = cloud*NP + (int)(unsigned)(bv & 0xffffffffull);
                cb[bp] = ~0ull;
            }
            __syncwarp();
        }
        if (lane == 0) d_cnt[cg] = KNBR;
    }
}

// ---------------- K3: h1 build + FFMA2 GEMM (conflict-free) + max -------------
// block = NTILE tiles of 2 centers each; 256 threads; thread tile 8m x 8n
// n-mapping interleaved: acc[j][p] covers m=tm*8+j, n-pair (2*tn+32*p, +1)
#define NTILE   4
#define OA      0                   // A dup: [k 128][j 8][tm 16] f32x2 = 131072 B
#define OB      131072              // B h1: [k 128][n 128] f32 = 65536 B (part reuse)
#define OWB     (OB + 65536)        // float4[128]: (b1, w1x, w1y, w1z)
#define ODP     (OWB + 2048)        // float4[128]: dpos per column
#define OGJ     (ODP + 2048)        // int[128]
#define K3_SMEM (OGJ + 512)         // 201216 B

__global__ __launch_bounds__(256, 1)
void k3_mlp(const float* __restrict__ pos,
            const float* __restrict__ W1, const float* __restrict__ b1,
            const float* __restrict__ W2, const float* __restrict__ b2,
            float* __restrict__ out)
{
    extern __shared__ char smem[];
    uint32_t sbase = smem_u32(smem);
    int t = threadIdx.x;

    // A = W2 (row-major [k][m]) pre-duplicated (w,w), j-major layout
    for (int idx = t; idx < HH*HH; idx += 256) {
        int k = idx >> 7, m = idx & 127;
        float wv = W2[idx];
        int tm = m >> 3, j = m & 7;
        *(unsigned long long*)(smem + OA + k*1024 + j*128 + tm*8) = packf2(wv, wv);
    }
    if (t < HH) {
        float4 wb;
        wb.x = b1[t];
        wb.y = W1[64*HH + t]; wb.z = W1[65*HH + t]; wb.w = W1[66*HH + t];
        *(float4*)(smem + OWB + t*16) = wb;
    }
    float b2m = b2[t & 127];

    int tm = t & 15, tn = t >> 4;

    for (int it = 0; it < NTILE; ++it) {
        int tile = blockIdx.x * NTILE + it;
        int cg0 = tile * 2;
        __syncthreads();   // prev tile's part reads done / A ready

        if (t < HH) {
            int cgx = cg0 + (t >> 6);
            int gj = d_nbr[cgx*KNBR + (t & 63)];
            *(int*)(smem + OGJ + t*4) = gj;
            float4 dp;
            dp.x = pos[(size_t)gj*3+0] - d_ctr[cgx*3+0];
            dp.y = pos[(size_t)gj*3+1] - d_ctr[cgx*3+1];
            dp.z = pos[(size_t)gj*3+2] - d_ctr[cgx*3+2];
            dp.w = 0.f;
            *(float4*)(smem + ODP + t*16) = dp;
        }
        __syncthreads();

        // build B: h1[k][n], thread = (col n = t&127, k-half = t>>7)
        {
            int n = t & 127, kh = t >> 7;
            int gj = *(int*)(smem + OGJ + n*4);
            float4 dp = *(float4*)(smem + ODP + n*16);
            const float4* grow = (const float4*)(g_feat + (size_t)gj*HH + kh*64);
            const float4* swb = (const float4*)(smem + OWB);
            float* sB = (float*)(smem + OB);
            #pragma unroll 4
            for (int q = 0; q < 16; ++q) {
                float4 g4 = __ldg(grow + q);
                int k0 = kh*64 + q*4;
                float gv[4] = {g4.x, g4.y, g4.z, g4.w};
                #pragma unroll
                for (int r = 0; r < 4; ++r) {
                    float4 wb = swb[k0 + r];
                    float v = gv[r] + wb.x;
                    v = fmaf(dp.x, wb.y, v);
                    v = fmaf(dp.y, wb.z, v);
                    v = fmaf(dp.z, wb.w, v);
                    sB[(k0 + r)*HH + n] = fmaxf(v, 0.0f);
                }
            }
        }
        __syncthreads();

        // GEMM: conflict-free B loads at tn*8 + p*128
        uint32_t aB = sbase + OA + tm*8;
        uint32_t bB = sbase + OB + tn*8;
        unsigned long long acc[8][4];
        #pragma unroll
        for (int j = 0; j < 8; ++j)
            #pragma unroll
            for (int p = 0; p < 4; ++p) acc[j][p] = 0ull;

        #pragma unroll 2
        for (int k = 0; k < HH; ++k) {
            unsigned long long a[8], b[4];
            LDSH64(a[0], aB, 0);   LDSH64(a[1], aB, 128);
            LDSH64(a[2], aB, 256); LDSH64(a[3], aB, 384);
            LDSH64(a[4], aB, 512); LDSH64(a[5], aB, 640);
            LDSH64(a[6], aB, 768); LDSH64(a[7], aB, 896);
            LDSH64(b[0], bB, 0);   LDSH64(b[1], bB, 128);
            LDSH64(b[2], bB, 256); LDSH64(b[3], bB, 384);
            #pragma unroll
            for (int j = 0; j < 8; ++j)
                #pragma unroll
                for (int p = 0; p < 4; ++p)
                    acc[j][p] = ffma2(a[j], b[p], acc[j][p]);
            aB += 1024; bB += 512;
        }
        __syncthreads();   // B dead; part reuses OB

        // per-thread partials: for each j, max over p{0,1} -> center0, p{2,3} -> center1
        {
            float* part = (float*)(smem + OB);   // [2 c][16 tn][128 m]
            #pragma unroll
            for (int j = 0; j < 8; ++j) {
                float l0,h0,l1,h1;
                unpackf2(acc[j][0], l0, h0); unpackf2(acc[j][1], l1, h1);
                float c0 = fmaxf(fmaxf(l0,h0), fmaxf(l1,h1));
                unpackf2(acc[j][2], l0, h0); unpackf2(acc[j][3], l1, h1);
                float c1 = fmaxf(fmaxf(l0,h0), fmaxf(l1,h1));
                int m = tm*8 + j;
                part[(0*16 + tn)*HH + m] = c0;
                part[(1*16 + tn)*HH + m] = c1;
            }
        }
        __syncthreads();

        // final reduce over tn: thread -> (center c, channel m)
        {
            const float* part = (const float*)(smem + OB);
            int c = t >> 7, m = t & 127;
            float mx = part[(c*16)*HH + m];
            #pragma unroll
            for (int i = 1; i < 16; ++i)
                mx = fmaxf(mx, part[(c*16 + i)*HH + m]);
            out[(size_t)(cg0 + c)*HH + m] = fmaxf(mx + b2m, 0.0f);
        }
    }
}

__global__ void k_fill(float* out, int start, int n) {
    int i = blockIdx.x * 256 + threadIdx.x;
    if (i < n) out[start + i] = 0.0f;
}

// ---------------- launch --------------------------------------------------
extern "C" void kernel_launch(void* const* d_in, const int* in_sizes, int n_in,
                              void* d_out, int out_size)
{
    const float* x   = (const float*)d_in[0];
    const float* pos = (const float*)d_in[1];
    const float* W1  = (const float*)d_in[2];
    const float* b1  = (const float*)d_in[3];
    const float* W2  = (const float*)d_in[4];
    const float* b2  = (const float*)d_in[5];
    float* out = (float*)d_out;

    size_t sm1 = 3*NP*4 + 128;
    size_t smg = (64*HH + 32*CIN)*4;
    if (smg > sm1) sm1 = smg;
    size_t sm2 = 3*NP*4 + 8*(size_t)CAP*8;
    size_t sm3 = K3_SMEM;
    cudaFuncSetAttribute(k1_fps_g, cudaFuncAttributeMaxDynamicSharedMemorySize, (int)sm1);
    cudaFuncSetAttribute(k2_ball,  cudaFuncAttributeMaxDynamicSharedMemorySize, (int)sm2);
    cudaFuncSetAttribute(k3_mlp,   cudaFuncAttributeMaxDynamicSharedMemorySize, (int)sm3);

    int mode = 0;
    int used = NC*HH;
    if (out_size >= NC*HH + NC*3)      { mode |= 1; used = NC*HH + NC*3; }
    if (out_size >= NC*HH + NC*3 + NC) { mode |= 2; used = NC*HH + NC*3 + NC; }

    k1_fps_g<<<BB + 1024, 256, sm1>>>(pos, x, W1);
    k2_ball<<<NC/8, 256, sm2>>>(pos, out, mode);
    k3_mlp<<<(NC/2)/NTILE, 256, sm3>>>(pos, W1, b1, W2, b2, out);

    if (out_size > used) {
        int n = out_size - used;
        k_fill<<<(n + 255)/256, 256>>>(out, used, n);
    }
}

// round 6
// speedup vs baseline: 1.8861x; 1.0364x over previous
#include <cuda_runtime.h>
#include <cstdint>

#define BB      8
#define NP      4096
#define NS      1024
#define NC      (BB*NS)
#define KNBR    64
#define CIN     64
#define HH      128
#define R2f     0.04f
#define CAP     768
#define NBALL   32
#define NGRID   148
#define NGTASK  1024
#define NBTASK  1024
#define NTTASK  4096

// ---------------- device scratch ----------------
__device__ float g_feat[BB*NP*HH];
__device__ int   fpsflag[NC];          // idx+1 when ready
__device__ int   ballflag[NC];         // 1 when nbr/ctr ready
__device__ int   d_nbr[NC*KNBR];       // padded to 64 (dup of nbr 0)
__device__ float d_ctr[NC*3];
__device__ int   d_sync[4];            // 0:g_ctr 1:ball_ctr 2:gemm_ctr 3:g_done

// ---------------- helpers ----------------
__device__ __forceinline__ float dist2(float ax,float ay,float az,float bx,float by,float bz){
    float dx = ax-bx, dy = ay-by, dz = az-bz;
    return __fadd_rn(__fadd_rn(__fmul_rn(dx,dx),__fmul_rn(dy,dy)),__fmul_rn(dz,dz));
}
__device__ __forceinline__ unsigned long long packf2(float lo, float hi){
    unsigned long long r; asm("mov.b64 %0, {%1, %2};" : "=l"(r) : "f"(lo), "f"(hi)); return r;
}
__device__ __forceinline__ void unpackf2(unsigned long long v, float& lo, float& hi){
    asm("mov.b64 {%0, %1}, %2;" : "=f"(lo), "=f"(hi) : "l"(v));
}
__device__ __forceinline__ unsigned long long addf2(unsigned long long a, unsigned long long b){
    unsigned long long d; asm("add.rn.f32x2 %0, %1, %2;" : "=l"(d) : "l"(a), "l"(b)); return d;
}
__device__ __forceinline__ unsigned long long mulf2(unsigned long long a, unsigned long long b){
    unsigned long long d; asm("mul.rn.f32x2 %0, %1, %2;" : "=l"(d) : "l"(a), "l"(b)); return d;
}
__device__ __forceinline__ unsigned long long ffma2(unsigned long long a, unsigned long long b, unsigned long long c){
    unsigned long long d; asm("fma.rn.f32x2 %0, %1, %2, %3;" : "=l"(d) : "l"(a), "l"(b), "l"(c)); return d;
}
__device__ __forceinline__ uint32_t smem_u32(const void* p){
    uint32_t a;
    asm("{ .reg .u64 t; cvta.to.shared.u64 t, %1; cvt.u32.u64 %0, t; }" : "=r"(a) : "l"(p));
    return a;
}
__device__ __forceinline__ int ld_acq(const int* p){
    int v; asm volatile("ld.acquire.gpu.s32 %0, [%1];" : "=r"(v) : "l"(p) : "memory"); return v;
}
__device__ __forceinline__ void st_rel(int* p, int v){
    asm volatile("st.release.gpu.s32 [%0], %1;" :: "l"(p), "r"(v) : "memory");
}
#define LDSH64(dst, addr, IMM) \
    asm volatile("ld.shared.b64 %0, [%1+%2];" : "=l"(dst) : "r"(addr), "n"(IMM))

// ---------------- smem layout (max 201 KB) ----------------
#define OA      0                    // GEMM A dup: 131072 B  | FPS pos 48KB | ball pos+cand 96KB | g sW+sx 40KB
#define OB      131072               // GEMM B: 65536 B (partials reuse)
#define OWB     (OB + 65536)         // float4[128]
#define ODP     (OWB + 2048)         // float4[128]
#define OGJ     (ODP + 2048)         // int[128]
#define OTASK   (OGJ + 512)          // int task broadcast
#define SM_TOT  (OTASK + 16)

// ================= roles =================
__device__ void fps_role(char* smem, const float* __restrict__ pos, int b)
{
    float* px = (float*)smem;
    float* py = px + NP;
    float* pz = py + NP;
    unsigned long long* sbuf = (unsigned long long*)(pz + NP); // [2][8]
    int tid = threadIdx.x;

    const float* pb = pos + (size_t)b*NP*3;
    for (int i = tid; i < NP; i += 256) {
        px[i] = pb[i*3+0]; py[i] = pb[i*3+1]; pz[i] = pb[i*3+2];
    }
    if (tid == 0) st_rel(&fpsflag[b*NS], 1);   // sample 0 = point 0
    __syncthreads();

    int ibase = tid << 4;
    unsigned long long rpx[8], rpy[8], rpz[8];
    float md[16];
    #pragma unroll
    for (int j = 0; j < 8; ++j) {
        rpx[j] = packf2(px[ibase+2*j], px[ibase+2*j+1]);
        rpy[j] = packf2(py[ibase+2*j], py[ibase+2*j+1]);
        rpz[j] = packf2(pz[ibase+2*j], pz[ibase+2*j+1]);
    }
    #pragma unroll
    for (int t = 0; t < 16; ++t) md[t] = 1e10f;

    int lane = tid & 31, warp = tid >> 5;
    int last = 0;
    for (int s = 1; s < NS; ++s) {
        float lx = px[last], ly = py[last], lz = pz[last];
        unsigned long long nx = packf2(-lx,-lx), ny = packf2(-ly,-ly), nz = packf2(-lz,-lz);
        #pragma unroll
        for (int j = 0; j < 8; ++j) {
            unsigned long long dx = addf2(rpx[j], nx);
            unsigned long long dy = addf2(rpy[j], ny);
            unsigned long long dz = addf2(rpz[j], nz);
            unsigned long long sD = addf2(addf2(mulf2(dx,dx), mulf2(dy,dy)), mulf2(dz,dz));
            float s0, s1; unpackf2(sD, s0, s1);
            md[2*j]   = fminf(md[2*j],   s0);
            md[2*j+1] = fminf(md[2*j+1], s1);
        }
        float bv = md[0]; int bt = 0;
        #pragma unroll
        for (int t = 1; t < 16; ++t)
            if (md[t] > bv) { bv = md[t]; bt = t; }

        unsigned vbits = __float_as_uint(bv);
        unsigned vm = __reduce_max_sync(0xffffffffu, vbits);
        unsigned msk = __ballot_sync(0xffffffffu, vbits == vm);
        int src = __ffs(msk) - 1;
        int bidx = __shfl_sync(0xffffffffu, ibase + bt, src);

        unsigned long long* slot = sbuf + (s & 1)*8;
        if (lane == 0)
            slot[warp] = ((unsigned long long)vm << 32) | (unsigned)(NP - 1 - bidx);
        __syncthreads();
        unsigned long long w = slot[0];
        #pragma unroll
        for (int k = 1; k < 8; ++k) { unsigned long long v = slot[k]; if (v > w) w = v; }
        last = NP - 1 - (int)(unsigned)(w & 0xffffffffull);
        if (tid == 0) st_rel(&fpsflag[b*NS + s], last + 1);
    }
}

__device__ void ball_role(char* smem, const float* __restrict__ pos,
                          float* __restrict__ out, int mode)
{
    float* px = (float*)smem;
    float* py = px + NP;
    float* pz = py + NP;
    unsigned long long* cball = (unsigned long long*)(pz + NP);
    int* stask = (int*)(smem + OTASK);
    int tid = threadIdx.x, lane = tid & 31, wid = tid >> 5;

    for (;;) {
        __syncthreads();          // protect smem from previous task
        if (tid == 0) *stask = atomicAdd(&d_sync[1], 1);
        __syncthreads();
        int c = *stask;
        if (c >= NBTASK) break;
        int cloud = c & 7, lc = c >> 3;

        const float* pb = pos + (size_t)cloud*NP*3;
        for (int i = tid; i < NP; i += 256) {
            px[i] = pb[i*3+0]; py[i] = pb[i*3+1]; pz[i] = pb[i*3+2];
        }
        __syncthreads();

        int cg = cloud*NS + lc*8 + wid;

        int v = 0;
        if (lane == 0) while ((v = ld_acq(&fpsflag[cg])) == 0) {}
        v = __shfl_sync(0xffffffffu, v, 0);
        int ci = v - 1;

        float cx = px[ci], cy = py[ci], cz = pz[ci];
        if (lane == 0) {
            d_ctr[cg*3+0] = cx; d_ctr[cg*3+1] = cy; d_ctr[cg*3+2] = cz;
            if (mode & 1) {
                out[NC*HH + cg*3+0] = cx;
                out[NC*HH + cg*3+1] = cy;
                out[NC*HH + cg*3+2] = cz;
            }
            if (mode & 2) out[NC*HH + NC*3 + cg] = (float)cloud;
        }

        unsigned long long* cb = cball + (size_t)wid * CAP;
        unsigned cnt = 0;
        for (int j = lane; j < NP; j += 32) {
            float d2 = dist2(px[j],py[j],pz[j],cx,cy,cz);
            bool in = (d2 <= R2f);
            unsigned m = __ballot_sync(0xffffffffu, in);
            if (in) {
                unsigned o = cnt + __popc(m & ((1u << lane) - 1u));
                if (o < CAP)
                    cb[o] = ((unsigned long long)__float_as_uint(d2) << 32) | (unsigned)j;
            }
            cnt += __popc(m);
        }
        if (cnt > CAP) cnt = CAP;

        int base = cg * KNBR;
        if (cnt <= KNBR) {
            int firstIdx = cloud*NP + (int)(unsigned)(cb[0] & 0xffffffffull);
            for (int t = lane; t < KNBR; t += 32)
                d_nbr[base + t] = (t < (int)cnt)
                    ? cloud*NP + (int)(unsigned)(cb[t] & 0xffffffffull) : firstIdx;
        } else {
            for (int t = 0; t < KNBR; ++t) {
                unsigned long long bv = ~0ull; int bp = -1;
                for (int p = lane; p < (int)cnt; p += 32) {
                    unsigned long long vv = cb[p];
                    if (vv < bv) { bv = vv; bp = p; }
                }
                #pragma unroll
                for (int off = 16; off; off >>= 1) {
                    unsigned long long ov = __shfl_xor_sync(0xffffffffu, bv, off);
                    int op = __shfl_xor_sync(0xffffffffu, bp, off);
                    if (ov < bv) { bv = ov; bp = op; }
                }
                if (lane == 0) {
                    d_nbr[base + t] = cloud*NP + (int)(unsigned)(bv & 0xffffffffull);
                    cb[bp] = ~0ull;
                }
                __syncwarp();
            }
        }
        __threadfence();
        __syncwarp();
        if (lane == 0) st_rel(&ballflag[cg], 1);
    }
}

__device__ void g_role(char* smem, const float* __restrict__ x,
                       const float* __restrict__ W1)
{
    float* sW = (float*)smem;            // 64*128
    float* sx = sW + 64*HH;              // 32*64
    int* stask = (int*)(smem + OTASK);
    int tid = threadIdx.x;
    int ndone = 0;

    for (int i = tid; i < 64*HH; i += 256) sW[i] = W1[i];

    for (;;) {
        __syncthreads();
        if (tid == 0) *stask = atomicAdd(&d_sync[0], 1);
        __syncthreads();
        int task = *stask;
        if (task >= NGTASK) break;
        int rbase = task * 32;
        for (int i = tid; i < 32*CIN; i += 256) {
            int r = i >> 6, c = i & 63;
            sx[i] = x[(size_t)(rbase + r)*CIN + c];
        }
        __syncthreads();
        #pragma unroll
        for (int pimg = 0; pimg < 16; ++pimg) {
            int o = tid + pimg*256;
            int r = o >> 7, col = o & 127;
            float acc = 0.0f;
            const float* xr = sx + r*CIN;
            #pragma unroll 16
            for (int c = 0; c < CIN; ++c)
                acc = fmaf(xr[c], sW[c*HH + col], acc);
            g_feat[(size_t)(rbase + r)*HH + col] = acc;
        }
        ++ndone;
    }
    __threadfence();
    __syncthreads();
    if (tid == 0 && ndone) atomicAdd(&d_sync[3], ndone);
}

__device__ void gemm_role(char* smem, const float* __restrict__ pos,
                          const float* __restrict__ W1, const float* __restrict__ b1,
                          const float* __restrict__ W2, const float* __restrict__ b2,
                          float* __restrict__ out)
{
    uint32_t sbase = smem_u32(smem);
    int t = threadIdx.x;
    int* stask = (int*)(smem + OTASK);

    // gate: all g_feat ready
    if (t == 0) while (ld_acq(&d_sync[3]) < NGTASK) {}
    __syncthreads();

    // A = W2 dup (w,w), j-major; OWB
    for (int idx = t; idx < HH*HH; idx += 256) {
        int k = idx >> 7, m = idx & 127;
        float wv = W2[idx];
        int tm = m >> 3, j = m & 7;
        *(unsigned long long*)(smem + OA + k*1024 + j*128 + tm*8) = packf2(wv, wv);
    }
    if (t < HH) {
        float4 wb;
        wb.x = b1[t];
        wb.y = W1[64*HH + t]; wb.z = W1[65*HH + t]; wb.w = W1[66*HH + t];
        *(float4*)(smem + OWB + t*16) = wb;
    }
    float b2m = b2[t & 127];
    int tm = t & 15, tn = t >> 4;

    for (;;) {
        __syncthreads();          // A ready / prev partial reads done
        if (t == 0) *stask = atomicAdd(&d_sync[2], 1);
        __syncthreads();
        int tile = *stask;
        if (tile >= NTTASK) break;
        int cloud = tile & 7, lt = tile >> 3;
        int cg0 = cloud*NS + lt*2;

        if (t < 2) { while (ld_acq(&ballflag[cg0 + t]) == 0) {} }
        __syncthreads();

        if (t < HH) {
            int cgx = cg0 + (t >> 6);
            int gj = d_nbr[cgx*KNBR + (t & 63)];
            *(int*)(smem + OGJ + t*4) = gj;
            float4 dp;
            dp.x = pos[(size_t)gj*3+0] - d_ctr[cgx*3+0];
            dp.y = pos[(size_t)gj*3+1] - d_ctr[cgx*3+1];
            dp.z = pos[(size_t)gj*3+2] - d_ctr[cgx*3+2];
            dp.w = 0.f;
            *(float4*)(smem + ODP + t*16) = dp;
        }
        __syncthreads();

        // B build
        {
            int n = t & 127, kh = t >> 7;
            int gj = *(int*)(smem + OGJ + n*4);
            float4 dp = *(float4*)(smem + ODP + n*16);
            const float4* grow = (const float4*)(g_feat + (size_t)gj*HH + kh*64);
            const float4* swb = (const float4*)(smem + OWB);
            float* sB = (float*)(smem + OB);
            #pragma unroll 4
            for (int q = 0; q < 16; ++q) {
                float4 g4 = __ldg(grow + q);
                int k0 = kh*64 + q*4;
                float gv[4] = {g4.x, g4.y, g4.z, g4.w};
                #pragma unroll
                for (int r = 0; r < 4; ++r) {
                    float4 wb = swb[k0 + r];
                    float v = gv[r] + wb.x;
                    v = fmaf(dp.x, wb.y, v);
                    v = fmaf(dp.y, wb.z, v);
                    v = fmaf(dp.z, wb.w, v);
                    sB[(k0 + r)*HH + n] = fmaxf(v, 0.0f);
                }
            }
        }
        __syncthreads();

        // GEMM, double-buffered
        uint32_t aB = sbase + OA + tm*8;
        uint32_t bB = sbase + OB + tn*8;
        unsigned long long acc[8][4];
        #pragma unroll
        for (int j = 0; j < 8; ++j)
            #pragma unroll
            for (int p = 0; p < 4; ++p) acc[j][p] = 0ull;

        unsigned long long a0[8], b0[4], a1[8], b1v[4];
        LDSH64(a0[0], aB, 0);   LDSH64(a0[1], aB, 128);
        LDSH64(a0[2], aB, 256); LDSH64(a0[3], aB, 384);
        LDSH64(a0[4], aB, 512); LDSH64(a0[5], aB, 640);
        LDSH64(a0[6], aB, 768); LDSH64(a0[7], aB, 896);
        LDSH64(b0[0], bB, 0);   LDSH64(b0[1], bB, 128);
        LDSH64(b0[2], bB, 256); LDSH64(b0[3], bB, 384);

        #pragma unroll 1
        for (int k = 0; k < HH; k += 2) {
            aB += 1024; bB += 512;
            LDSH64(a1[0], aB, 0);   LDSH64(a1[1], aB, 128);
            LDSH64(a1[2], aB, 256); LDSH64(a1[3], aB, 384);
            LDSH64(a1[4], aB, 512); LDSH64(a1[5], aB, 640);
            LDSH64(a1[6], aB, 768); LDSH64(a1[7], aB, 896);
            LDSH64(b1v[0], bB, 0);   LDSH64(b1v[1], bB, 128);
            LDSH64(b1v[2], bB, 256); LDSH64(b1v[3], bB, 384);
            #pragma unroll
            for (int j = 0; j < 8; ++j)
                #pragma unroll
                for (int p = 0; p < 4; ++p)
                    acc[j][p] = ffma2(a0[j], b0[p], acc[j][p]);
            aB += 1024; bB += 512;
            LDSH64(a0[0], aB, 0);   LDSH64(a0[1], aB, 128);
            LDSH64(a0[2], aB, 256); LDSH64(a0[3], aB, 384);
            LDSH64(a0[4], aB, 512); LDSH64(a0[5], aB, 640);
            LDSH64(a0[6], aB, 768); LDSH64(a0[7], aB, 896);
            LDSH64(b0[0], bB, 0);   LDSH64(b0[1], bB, 128);
            LDSH64(b0[2], bB, 256); LDSH64(b0[3], bB, 384);
            #pragma unroll
            for (int j = 0; j < 8; ++j)
                #pragma unroll
                for (int p = 0; p < 4; ++p)
                    acc[j][p] = ffma2(a1[j], b1v[p], acc[j][p]);
        }
        __syncthreads();   // B dead; partials reuse OB

        {
            float* part = (float*)(smem + OB);   // [2 c][16 tn][128 m]
            #pragma unroll
            for (int j = 0; j < 8; ++j) {
                float l0,h0,l1,h1;
                unpackf2(acc[j][0], l0, h0); unpackf2(acc[j][1], l1, h1);
                float c0 = fmaxf(fmaxf(l0,h0), fmaxf(l1,h1));
                unpackf2(acc[j][2], l0, h0); unpackf2(acc[j][3], l1, h1);
                float c1 = fmaxf(fmaxf(l0,h0), fmaxf(l1,h1));
                int m = tm*8 + j;
                part[(0*16 + tn)*HH + m] = c0;
                part[(1*16 + tn)*HH + m] = c1;
            }
        }
        __syncthreads();

        {
            const float* part = (const float*)(smem + OB);
            int c = t >> 7, m = t & 127;
            float mx = part[(c*16)*HH + m];
            #pragma unroll
            for (int i = 1; i < 16; ++i)
                mx = fmaxf(mx, part[(c*16 + i)*HH + m]);
            out[(size_t)(cg0 + c)*HH + m] = fmaxf(mx + b2m, 0.0f);
        }
    }
}

// ================= megakernel =================
__global__ __launch_bounds__(256, 1)
void mega(const float* __restrict__ x, const float* __restrict__ pos,
          const float* __restrict__ W1, const float* __restrict__ b1,
          const float* __restrict__ W2, const float* __restrict__ b2,
          float* __restrict__ out, int mode)
{
    extern __shared__ char smem[];
    int bid = blockIdx.x;

    if (bid < BB) {
        fps_role(smem, pos, bid);
    } else if (bid < BB + NBALL) {
        ball_role(smem, pos, out, mode);
    } else {
        g_role(smem, x, W1);
    }
    __syncthreads();
    gemm_role(smem, pos, W1, b1, W2, b2, out);
}

__global__ void k_fill(float* out, int start, int n) {
    int i = blockIdx.x * 256 + threadIdx.x;
    if (i < n) out[start + i] = 0.0f;
}

// ---------------- launch --------------------------------------------------
extern "C" void kernel_launch(void* const* d_in, const int* in_sizes, int n_in,
                              void* d_out, int out_size)
{
    const float* x   = (const float*)d_in[0];
    const float* pos = (const float*)d_in[1];
    const float* W1  = (const float*)d_in[2];
    const float* b1  = (const float*)d_in[3];
    const float* W2  = (const float*)d_in[4];
    const float* b2  = (const float*)d_in[5];
    float* out = (float*)d_out;

    void *p_fps, *p_ball, *p_sync;
    cudaGetSymbolAddress(&p_fps,  fpsflag);
    cudaGetSymbolAddress(&p_ball, ballflag);
    cudaGetSymbolAddress(&p_sync, d_sync);
    cudaMemsetAsync(p_fps,  0, NC*sizeof(int));
    cudaMemsetAsync(p_ball, 0, NC*sizeof(int));
    cudaMemsetAsync(p_sync, 0, 4*sizeof(int));

    cudaFuncSetAttribute(mega, cudaFuncAttributeMaxDynamicSharedMemorySize, SM_TOT);

    int mode = 0;
    int used = NC*HH;
    if (out_size >= NC*HH + NC*3)      { mode |= 1; used = NC*HH + NC*3; }
    if (out_size >= NC*HH + NC*3 + NC) { mode |= 2; used = NC*HH + NC*3 + NC; }

    mega<<<NGRID, 256, SM_TOT>>>(x, pos, W1, b1, W2, b2, out, mode);

    if (out_size > used) {
        int n = out_size - used;
        k_fill<<<(n + 255)/256, 256>>>(out, used, n);
    }
}